// round 5
// baseline (speedup 1.0000x reference)
#include <cuda_runtime.h>
#include <math.h>

#define N_NODES 10000
#define N_EDGES 640000
#define FDIM    128
#define TE      64      // edges (or nodes) per block
#define LDI     260     // smem stride for edge input tile (256 + 4 pad)
#define LDH     132     // smem stride for hidden tile (128 + 4 pad)
#define LDN     388     // smem stride for node input tile (384 + 4 pad)

// scratch for segment-sum aggregate (no cudaMalloc allowed)
__device__ float g_agg[N_NODES * FDIM];

__device__ __forceinline__ float sigmoidf_(float x) { return 1.0f / (1.0f + __expf(-x)); }
__device__ __forceinline__ float softsignf_(float x) { return x / (1.0f + fabsf(x)); }

// inline function instead of macro: avoids the .w-field / macro-param-w
// token-substitution bug that broke the R3 build.
__device__ __forceinline__ void fma4(float4& acc, float s, const float4& v) {
    acc.x = fmaf(s, v.x, acc.x);
    acc.y = fmaf(s, v.y, acc.y);
    acc.z = fmaf(s, v.z, acc.z);
    acc.w = fmaf(s, v.w, acc.w);
}

__global__ void zero_agg_kernel() {
    int i = blockIdx.x * blockDim.x + threadIdx.x;
    if (i < N_NODES * FDIM) g_agg[i] = 0.0f;
}

// ---------------------------------------------------------------------------
// Edge kernel: gather src/dst features -> sigmoid([src,dst]@Wm1+bm1)
//              -> softsign(h@Wm2+bm2) -> atomic scatter-add into g_agg[rows]
// Block: 64 edges x 128 outputs. Thread (tx,ty): tx in [0,32) over output
// quads, ty in [0,8) over 8-edge groups. 32 fp32 accumulators per thread.
// ---------------------------------------------------------------------------
__global__ void __launch_bounds__(256, 2)
edge_kernel(const float* __restrict__ features,
            const int*   __restrict__ rows,
            const int*   __restrict__ cols,
            const float* __restrict__ Wm1,
            const float* __restrict__ bm1,
            const float* __restrict__ Wm2,
            const float* __restrict__ bm2)
{
    extern __shared__ float smem[];
    float* sIn  = smem;                          // TE x LDI floats
    int*   sRow = (int*)(smem + TE * LDI);       // TE
    int*   sCol = sRow + TE;                     // TE

    const int tid = threadIdx.x;
    const int tx  = tid & 31;        // lane: output quad index
    const int ty  = tid >> 5;        // warp: edge group
    const int e0  = blockIdx.x * TE;

    if (tid < TE) { sRow[tid] = rows[e0 + tid]; sCol[tid] = cols[e0 + tid]; }
    __syncthreads();

    // Gather: one warp per edge (8 edges per warp), lane covers 4 floats.
    // Streaming loads keep L1 free for the weight matrices.
    for (int e = ty; e < TE; e += 8) {
        const float4* sp = (const float4*)(features + (size_t)sRow[e] * FDIM);
        const float4* dp = (const float4*)(features + (size_t)sCol[e] * FDIM);
        float4 s = __ldcs(sp + tx);
        float4 d = __ldcs(dp + tx);
        *(float4*)&sIn[e * LDI + tx * 4]        = s;
        *(float4*)&sIn[e * LDI + FDIM + tx * 4] = d;
    }
    __syncthreads();

    // ---- GEMM1: [64,256] @ Wm1[256,128] ----
    float4 acc[8];
    #pragma unroll
    for (int e = 0; e < 8; e++) acc[e] = make_float4(0.f, 0.f, 0.f, 0.f);

    const float4* W1v   = (const float4*)Wm1;
    const float*  aBase = sIn + (ty * 8) * LDI;

    #pragma unroll 2
    for (int k = 0; k < 2 * FDIM; k += 4) {
        float4 w0 = __ldg(W1v + (k + 0) * 32 + tx);
        float4 w1 = __ldg(W1v + (k + 1) * 32 + tx);
        float4 w2 = __ldg(W1v + (k + 2) * 32 + tx);
        float4 w3 = __ldg(W1v + (k + 3) * 32 + tx);
        #pragma unroll
        for (int e = 0; e < 8; e++) {
            float4 a = *(const float4*)(aBase + e * LDI + k);
            fma4(acc[e], a.x, w0);
            fma4(acc[e], a.y, w1);
            fma4(acc[e], a.z, w2);
            fma4(acc[e], a.w, w3);
        }
    }
    __syncthreads();   // everyone done reading sIn before H overlays it

    // ---- epilogue 1: h = sigmoid(acc + bm1), write to smem (overlay) ----
    float4 b1 = __ldg((const float4*)bm1 + tx);
    float* sH = smem;  // TE x LDH floats, fits inside the sIn footprint
    #pragma unroll
    for (int e = 0; e < 8; e++) {
        float4 h;
        h.x = sigmoidf_(acc[e].x + b1.x);
        h.y = sigmoidf_(acc[e].y + b1.y);
        h.z = sigmoidf_(acc[e].z + b1.z);
        h.w = sigmoidf_(acc[e].w + b1.w);
        *(float4*)&sH[(ty * 8 + e) * LDH + tx * 4] = h;
    }
    __syncthreads();

    // ---- GEMM2: [64,128] @ Wm2[128,128] ----
    float4 acc2[8];
    #pragma unroll
    for (int e = 0; e < 8; e++) acc2[e] = make_float4(0.f, 0.f, 0.f, 0.f);

    const float4* W2v   = (const float4*)Wm2;
    const float*  hBase = sH + (ty * 8) * LDH;

    #pragma unroll 2
    for (int k = 0; k < FDIM; k += 4) {
        float4 w0 = __ldg(W2v + (k + 0) * 32 + tx);
        float4 w1 = __ldg(W2v + (k + 1) * 32 + tx);
        float4 w2 = __ldg(W2v + (k + 2) * 32 + tx);
        float4 w3 = __ldg(W2v + (k + 3) * 32 + tx);
        #pragma unroll
        for (int e = 0; e < 8; e++) {
            float4 a = *(const float4*)(hBase + e * LDH + k);
            fma4(acc2[e], a.x, w0);
            fma4(acc2[e], a.y, w1);
            fma4(acc2[e], a.z, w2);
            fma4(acc2[e], a.w, w3);
        }
    }

    // ---- epilogue 2: softsign + coalesced atomic scatter-add ----
    float4 b2 = __ldg((const float4*)bm2 + tx);
    #pragma unroll
    for (int e = 0; e < 8; e++) {
        int r = sRow[ty * 8 + e];
        float* dst = g_agg + (size_t)r * FDIM + tx * 4;
        atomicAdd(dst + 0, softsignf_(acc2[e].x + b2.x));
        atomicAdd(dst + 1, softsignf_(acc2[e].y + b2.y));
        atomicAdd(dst + 2, softsignf_(acc2[e].z + b2.z));
        atomicAdd(dst + 3, softsignf_(acc2[e].w + b2.w));
    }
}

// ---------------------------------------------------------------------------
// Node kernel: g = sigmoid([feat, agg, time]); g = sigmoid(g@Wf1+bf1);
//              out = softsign(g@Wf2+bf2)
// ---------------------------------------------------------------------------
__global__ void __launch_bounds__(256, 2)
node_kernel(const float* __restrict__ features,
            const float* __restrict__ time_emb,
            const float* __restrict__ Wf1,
            const float* __restrict__ bf1,
            const float* __restrict__ Wf2,
            const float* __restrict__ bf2,
            float* __restrict__ out)
{
    extern __shared__ float smem[];
    float* sIn = smem;   // TE x LDN floats

    const int tid = threadIdx.x;
    const int tx  = tid & 31;
    const int ty  = tid >> 5;
    const int n0  = blockIdx.x * TE;

    // Gather + first sigmoid applied during smem fill
    for (int n = ty; n < TE; n += 8) {
        int node = n0 + n;
        float4 a, g, t;
        if (node < N_NODES) {
            a = __ldg((const float4*)(features + (size_t)node * FDIM) + tx);
            g = *((const float4*)(g_agg + (size_t)node * FDIM) + tx);
            t = __ldg((const float4*)(time_emb + (size_t)node * FDIM) + tx);
        } else {
            a = g = t = make_float4(0.f, 0.f, 0.f, 0.f);
        }
        float4 sa = make_float4(sigmoidf_(a.x), sigmoidf_(a.y), sigmoidf_(a.z), sigmoidf_(a.w));
        float4 sg = make_float4(sigmoidf_(g.x), sigmoidf_(g.y), sigmoidf_(g.z), sigmoidf_(g.w));
        float4 st = make_float4(sigmoidf_(t.x), sigmoidf_(t.y), sigmoidf_(t.z), sigmoidf_(t.w));
        *(float4*)&sIn[n * LDN + tx * 4]            = sa;
        *(float4*)&sIn[n * LDN + FDIM + tx * 4]     = sg;
        *(float4*)&sIn[n * LDN + 2 * FDIM + tx * 4] = st;
    }
    __syncthreads();

    // ---- GEMM1: [64,384] @ Wf1[384,128] ----
    float4 acc[8];
    #pragma unroll
    for (int e = 0; e < 8; e++) acc[e] = make_float4(0.f, 0.f, 0.f, 0.f);

    const float4* W1v   = (const float4*)Wf1;
    const float*  aBase = sIn + (ty * 8) * LDN;

    #pragma unroll 2
    for (int k = 0; k < 3 * FDIM; k += 4) {
        float4 w0 = __ldg(W1v + (k + 0) * 32 + tx);
        float4 w1 = __ldg(W1v + (k + 1) * 32 + tx);
        float4 w2 = __ldg(W1v + (k + 2) * 32 + tx);
        float4 w3 = __ldg(W1v + (k + 3) * 32 + tx);
        #pragma unroll
        for (int e = 0; e < 8; e++) {
            float4 a = *(const float4*)(aBase + e * LDN + k);
            fma4(acc[e], a.x, w0);
            fma4(acc[e], a.y, w1);
            fma4(acc[e], a.z, w2);
            fma4(acc[e], a.w, w3);
        }
    }
    __syncthreads();   // reads of sIn done before H overlay

    float4 b1 = __ldg((const float4*)bf1 + tx);
    float* sH = smem;
    #pragma unroll
    for (int e = 0; e < 8; e++) {
        float4 h;
        h.x = sigmoidf_(acc[e].x + b1.x);
        h.y = sigmoidf_(acc[e].y + b1.y);
        h.z = sigmoidf_(acc[e].z + b1.z);
        h.w = sigmoidf_(acc[e].w + b1.w);
        *(float4*)&sH[(ty * 8 + e) * LDH + tx * 4] = h;
    }
    __syncthreads();

    // ---- GEMM2: [64,128] @ Wf2[128,128] ----
    float4 acc2[8];
    #pragma unroll
    for (int e = 0; e < 8; e++) acc2[e] = make_float4(0.f, 0.f, 0.f, 0.f);

    const float4* W2v   = (const float4*)Wf2;
    const float*  hBase = sH + (ty * 8) * LDH;

    #pragma unroll 2
    for (int k = 0; k < FDIM; k += 4) {
        float4 w0 = __ldg(W2v + (k + 0) * 32 + tx);
        float4 w1 = __ldg(W2v + (k + 1) * 32 + tx);
        float4 w2 = __ldg(W2v + (k + 2) * 32 + tx);
        float4 w3 = __ldg(W2v + (k + 3) * 32 + tx);
        #pragma unroll
        for (int e = 0; e < 8; e++) {
            float4 a = *(const float4*)(hBase + e * LDH + k);
            fma4(acc2[e], a.x, w0);
            fma4(acc2[e], a.y, w1);
            fma4(acc2[e], a.z, w2);
            fma4(acc2[e], a.w, w3);
        }
    }

    float4 b2 = __ldg((const float4*)bf2 + tx);
    #pragma unroll
    for (int e = 0; e < 8; e++) {
        int node = n0 + ty * 8 + e;
        if (node < N_NODES) {
            float4 o;
            o.x = softsignf_(acc2[e].x + b2.x);
            o.y = softsignf_(acc2[e].y + b2.y);
            o.z = softsignf_(acc2[e].z + b2.z);
            o.w = softsignf_(acc2[e].w + b2.w);
            *(float4*)(out + (size_t)node * FDIM + tx * 4) = o;
        }
    }
}

extern "C" void kernel_launch(void* const* d_in, const int* in_sizes, int n_in,
                              void* d_out, int out_size)
{
    const float* features = (const float*)d_in[0];
    const int*   rows     = (const int*)  d_in[1];
    const int*   cols     = (const int*)  d_in[2];
    const float* time_emb = (const float*)d_in[3];
    const float* Wm1      = (const float*)d_in[4];
    const float* bm1      = (const float*)d_in[5];
    const float* Wm2      = (const float*)d_in[6];
    const float* bm2      = (const float*)d_in[7];
    const float* Wf1      = (const float*)d_in[8];
    const float* bf1      = (const float*)d_in[9];
    const float* Wf2      = (const float*)d_in[10];
    const float* bf2      = (const float*)d_in[11];
    float* out = (float*)d_out;

    const int edge_smem = TE * LDI * sizeof(float) + 2 * TE * sizeof(int); // 67072 B
    const int node_smem = TE * LDN * sizeof(float);                        // 99328 B
    cudaFuncSetAttribute(edge_kernel, cudaFuncAttributeMaxDynamicSharedMemorySize, edge_smem);
    cudaFuncSetAttribute(node_kernel, cudaFuncAttributeMaxDynamicSharedMemorySize, node_smem);

    zero_agg_kernel<<<(N_NODES * FDIM + 255) / 256, 256>>>();
    edge_kernel<<<N_EDGES / TE, 256, edge_smem>>>(features, rows, cols, Wm1, bm1, Wm2, bm2);
    node_kernel<<<(N_NODES + TE - 1) / TE, 256, node_smem>>>(features, time_emb,
                                                             Wf1, bf1, Wf2, bf2, out);
}